// round 2
// baseline (speedup 1.0000x reference)
#include <cuda_runtime.h>
#include <cuda_bf16.h>
#include <cstdint>

// Problem dims
#define NB   32      // batch
#define CC   128     // channels (in == out)
#define HH_  56
#define WW_  56
#define HW_  (HH_*WW_)   // 3136
#define C4   (CC/4)      // 32 packed channel-groups

// ---------------- scratch (static device globals; no runtime allocs) -------
__device__ int g_xq [NB*C4*HW_];   // quantized x, packed 4 channels/word
__device__ int g_y1q[NB*C4*HW_];   // quantized conv1 output, same layout
__device__ int g_w1p[C4*9*CC];     // weights packed [ci4][k][co], 4 ci/word
__device__ int g_w2p[C4*9*CC];

static __device__ __forceinline__ int pack4(int a, int b, int c, int d) {
    return (a & 255) | ((b & 255) << 8) | ((c & 255) << 16) | ((d & 255) << 24);
}

// ---------------- kernel 1: quantize x and pack channels -------------------
// one thread per packed word: word idx = ((n*C4 + c4)*HW) + hw
__global__ void quant_x_kernel(const float* __restrict__ x) {
    int idx = blockIdx.x * 256 + threadIdx.x;
    if (idx >= NB * C4 * HW_) return;
    int hw = idx % HW_;
    int t  = idx / HW_;
    int c4 = t & (C4 - 1);
    int n  = t / C4;
    int word = 0;
#pragma unroll
    for (int l = 0; l < 4; ++l) {
        float v = x[(n * CC + c4 * 4 + l) * HW_ + hw];
        int q = (int)rintf(fminf(fmaxf(v * 32.0f, -128.0f), 127.0f));
        word |= (q & 255) << (8 * l);
    }
    g_xq[idx] = word;
}

// ---------------- kernel 2: pack both weight tensors -----------------------
// source layout  w[co][ci][kh][kw]  ->  dest [ci4][k][co] (4 ci per word)
__global__ void pack_w_kernel(const float* __restrict__ w1,
                              const float* __restrict__ w2) {
    int idx = blockIdx.x * 256 + threadIdx.x;
    const int PER = C4 * 9 * CC;   // 36864
    if (idx >= 2 * PER) return;
    const float* w = (idx < PER) ? w1 : w2;
    int*        op = (idx < PER) ? g_w1p : g_w2p;
    int o  = (idx < PER) ? idx : idx - PER;
    int co = o % CC;
    int k  = (o / CC) % 9;
    int c4 = o / (CC * 9);
    int word = 0;
#pragma unroll
    for (int l = 0; l < 4; ++l) {
        float v = w[(co * CC + c4 * 4 + l) * 9 + k];
        int q = (int)rintf(v);          // already integer-valued, in [-128,127]
        word |= (q & 255) << (8 * l);
    }
    op[o] = word;
}

// ---------------- conv core (dp4a, smem tiled), two epilogues --------------
// Block: one image n (blockIdx.z), 32 output channels (blockIdx.y of 4),
//        8 rows x 56 cols spatial tile (blockIdx.x of 7).
// 256 threads: pixg = tid&63 -> (row hh = pixg/8, 7 consecutive cols at
// wbase=(pixg%8)*7); cog = tid>>6 -> 8 output channels cog*8..cog*8+7.
// K loop: 4 chunks of 8 ci4 (=32 input channels each).
template <int PHASE>
__launch_bounds__(256, 2)
__global__ void conv_kernel(const float* __restrict__ xres,
                            float* __restrict__ out) {
    const int* __restrict__ in = (PHASE == 0) ? g_xq  : g_y1q;
    const int* __restrict__ wp = (PHASE == 0) ? g_w1p : g_w2p;

    const int n   = blockIdx.z;
    const int cb  = blockIdx.y;          // 0..3  (32 couts each)
    const int h0  = blockIdx.x * 8;      // 0..48
    const int tid = threadIdx.x;
    const int pixg  = tid & 63;
    const int cog   = tid >> 6;          // 0..3
    const int hh    = pixg >> 3;         // 0..7
    const int wbase = (pixg & 7) * 7;    // 0..49

    __shared__ int s_in[8][10][58];                 // 18.1 KB
    __shared__ __align__(16) int s_w[8][9][32];     //  9.0 KB

    int acc[8][7];
#pragma unroll
    for (int j = 0; j < 8; ++j)
#pragma unroll
        for (int p = 0; p < 7; ++p) acc[j][p] = 0;

    for (int chunk = 0; chunk < 4; ++chunk) {
        __syncthreads();
        // ---- stage input tile (8 ci4 x 10 rows x 58 cols, zero halo) ----
        for (int idx = tid; idx < 8 * 10 * 58; idx += 256) {
            int l   = idx / 580;
            int rem = idx - l * 580;
            int r   = rem / 58;
            int c   = rem - r * 58;
            int gh  = h0 + r - 1;
            int gw  = c - 1;
            int v = 0;
            if ((unsigned)gh < (unsigned)HH_ && (unsigned)gw < (unsigned)WW_)
                v = in[((n * C4 + chunk * 8 + l) * HH_ + gh) * WW_ + gw];
            s_in[l][r][c] = v;
        }
        // ---- stage weights (8 ci4 x 9 taps x 32 couts), coalesced ----
        for (int idx = tid; idx < 8 * 9 * 32; idx += 256) {
            int col = idx & 31;
            int k   = (idx >> 5) % 9;
            int l   = idx / 288;
            s_w[l][k][col] = wp[((chunk * 8 + l) * 9 + k) * CC + cb * 32 + col];
        }
        __syncthreads();

        // ---- dp4a mainloop: 504 dp4a per ci4-group per thread ----
#pragma unroll
        for (int l = 0; l < 8; ++l) {
#pragma unroll
            for (int kh = 0; kh < 3; ++kh) {
                int xr[9];
#pragma unroll
                for (int i = 0; i < 9; ++i) xr[i] = s_in[l][hh + kh][wbase + i];
#pragma unroll
                for (int kw = 0; kw < 3; ++kw) {
                    const int4* w4 =
                        (const int4*)&s_w[l][kh * 3 + kw][cog * 8];
                    int4 wa = w4[0], wb = w4[1];
                    int wv[8] = {wa.x, wa.y, wa.z, wa.w, wb.x, wb.y, wb.z, wb.w};
#pragma unroll
                    for (int j = 0; j < 8; ++j)
#pragma unroll
                        for (int p = 0; p < 7; ++p)
                            acc[j][p] = __dp4a(xr[kw + p], wv[j], acc[j][p]);
                }
            }
        }
    }

    const int h = h0 + hh;
    if (PHASE == 0) {
        // dequant (/2^11) -> relu -> requant to int8 @ fraclen 5 -> pack.
        // relu(acc/2048)*32 = max(acc,0)/64 ; clip upper 127 (lower inactive).
        const int co4 = (cb * 32 + cog * 8) >> 2;   // first packed group
#pragma unroll
        for (int p = 0; p < 7; ++p) {
            int w = wbase + p;
            int q[8];
#pragma unroll
            for (int j = 0; j < 8; ++j) {
                float y = (float)max(acc[j][p], 0) * (1.0f / 64.0f);
                q[j] = (int)rintf(fminf(y, 127.0f));
            }
            int base = ((n * C4 + co4) * HH_ + h) * WW_ + w;
            g_y1q[base]        = pack4(q[0], q[1], q[2], q[3]);
            g_y1q[base + HW_]  = pack4(q[4], q[5], q[6], q[7]);
        }
    } else {
        // residual in fixed-point scale 2^11 with int32-range clamp, relu.
        // res*2048 == (float)acc exactly; add x*2048, clamp, /2048, relu.
#pragma unroll
        for (int j = 0; j < 8; ++j) {
            int co = cb * 32 + cog * 8 + j;
#pragma unroll
            for (int p = 0; p < 7; ++p) {
                int w  = wbase + p;
                int gi = ((n * CC + co) * HH_ + h) * WW_ + w;
                float s = (float)acc[j][p] + xres[gi] * 2048.0f;
                s = fminf(fmaxf(s, -2147483647.0f), 2147483647.0f);
                out[gi] = fmaxf(s, 0.0f) * (1.0f / 2048.0f);
            }
        }
    }
}

// ---------------- launch ----------------------------------------------------
extern "C" void kernel_launch(void* const* d_in, const int* in_sizes, int n_in,
                              void* d_out, int out_size) {
    const float* x  = (const float*)d_in[0];
    const float* w1 = (const float*)d_in[1];
    const float* w2 = (const float*)d_in[2];
    float* out = (float*)d_out;

    {   // quantize + pack x
        int total = NB * C4 * HW_;
        quant_x_kernel<<<(total + 255) / 256, 256>>>(x);
    }
    {   // pack both weight tensors
        int total = 2 * C4 * 9 * CC;
        pack_w_kernel<<<(total + 255) / 256, 256>>>(w1, w2);
    }
    dim3 grid(HH_ / 8, CC / 32, NB);   // (7, 4, 32)
    conv_kernel<0><<<grid, 256>>>(nullptr, nullptr);
    conv_kernel<1><<<grid, 256>>>(x, out);
}

// round 3
// speedup vs baseline: 1.0005x; 1.0005x over previous
#include <cuda_runtime.h>
#include <cuda_bf16.h>
#include <cstdint>

// Problem dims
#define NB   32      // batch
#define CC   128     // channels (in == out)
#define HH_  56
#define WW_  56
#define HW_  (HH_*WW_)   // 3136
#define C4   (CC/4)      // 32 packed channel-groups

// ---------------- scratch (static device globals; no runtime allocs) -------
__device__ int g_xq [NB*C4*HW_];   // quantized x, packed 4 channels/word
__device__ int g_y1q[NB*C4*HW_];   // quantized conv1 output, same layout
__device__ int g_w1p[C4*9*CC];     // weights packed [ci4][k][co], 4 ci/word
__device__ int g_w2p[C4*9*CC];

static __device__ __forceinline__ int pack4(int a, int b, int c, int d) {
    return (a & 255) | ((b & 255) << 8) | ((c & 255) << 16) | ((d & 255) << 24);
}

// ---------------- kernel 1: quantize x and pack channels -------------------
// one thread per packed word: word idx = ((n*C4 + c4)*HW) + hw
__global__ void quant_x_kernel(const float* __restrict__ x) {
    int idx = blockIdx.x * 256 + threadIdx.x;
    if (idx >= NB * C4 * HW_) return;
    int hw = idx % HW_;
    int t  = idx / HW_;
    int c4 = t & (C4 - 1);
    int n  = t / C4;
    int word = 0;
#pragma unroll
    for (int l = 0; l < 4; ++l) {
        float v = x[(n * CC + c4 * 4 + l) * HW_ + hw];
        int q = (int)rintf(fminf(fmaxf(v * 32.0f, -128.0f), 127.0f));
        word |= (q & 255) << (8 * l);
    }
    g_xq[idx] = word;
}

// ---------------- kernel 2: pack both weight tensors -----------------------
// source layout  w[co][ci][kh][kw]  ->  dest [ci4][k][co] (4 ci per word)
__global__ void pack_w_kernel(const float* __restrict__ w1,
                              const float* __restrict__ w2) {
    int idx = blockIdx.x * 256 + threadIdx.x;
    const int PER = C4 * 9 * CC;   // 36864
    if (idx >= 2 * PER) return;
    const float* w = (idx < PER) ? w1 : w2;
    int*        op = (idx < PER) ? g_w1p : g_w2p;
    int o  = (idx < PER) ? idx : idx - PER;
    int co = o % CC;
    int k  = (o / CC) % 9;
    int c4 = o / (CC * 9);
    int word = 0;
#pragma unroll
    for (int l = 0; l < 4; ++l) {
        float v = w[(co * CC + c4 * 4 + l) * 9 + k];
        int q = (int)rintf(v);          // already integer-valued, in [-128,127]
        word |= (q & 255) << (8 * l);
    }
    op[o] = word;
}

// ---------------- conv core (dp4a, smem tiled), two epilogues --------------
// Block: one image n (blockIdx.z), 32 output channels (blockIdx.y of 4),
//        8 rows x 56 cols spatial tile (blockIdx.x of 7).
// 256 threads: pixg = tid&63 -> (row hh = pixg/8, 7 consecutive cols at
// wbase=(pixg%8)*7); cog = tid>>6 -> 8 output channels cog*8..cog*8+7.
// K loop: 4 chunks of 8 ci4 (=32 input channels each).
template <int PHASE>
__launch_bounds__(256, 2)
__global__ void conv_kernel(const float* __restrict__ xres,
                            float* __restrict__ out) {
    const int* __restrict__ in = (PHASE == 0) ? g_xq  : g_y1q;
    const int* __restrict__ wp = (PHASE == 0) ? g_w1p : g_w2p;

    const int n   = blockIdx.z;
    const int cb  = blockIdx.y;          // 0..3  (32 couts each)
    const int h0  = blockIdx.x * 8;      // 0..48
    const int tid = threadIdx.x;
    const int pixg  = tid & 63;
    const int cog   = tid >> 6;          // 0..3
    const int hh    = pixg >> 3;         // 0..7
    const int wbase = (pixg & 7) * 7;    // 0..49

    __shared__ int s_in[8][10][58];                 // 18.1 KB
    __shared__ __align__(16) int s_w[8][9][32];     //  9.0 KB

    int acc[8][7];
#pragma unroll
    for (int j = 0; j < 8; ++j)
#pragma unroll
        for (int p = 0; p < 7; ++p) acc[j][p] = 0;

    for (int chunk = 0; chunk < 4; ++chunk) {
        __syncthreads();
        // ---- stage input tile (8 ci4 x 10 rows x 58 cols, zero halo) ----
        for (int idx = tid; idx < 8 * 10 * 58; idx += 256) {
            int l   = idx / 580;
            int rem = idx - l * 580;
            int r   = rem / 58;
            int c   = rem - r * 58;
            int gh  = h0 + r - 1;
            int gw  = c - 1;
            int v = 0;
            if ((unsigned)gh < (unsigned)HH_ && (unsigned)gw < (unsigned)WW_)
                v = in[((n * C4 + chunk * 8 + l) * HH_ + gh) * WW_ + gw];
            s_in[l][r][c] = v;
        }
        // ---- stage weights (8 ci4 x 9 taps x 32 couts), coalesced ----
        for (int idx = tid; idx < 8 * 9 * 32; idx += 256) {
            int col = idx & 31;
            int k   = (idx >> 5) % 9;
            int l   = idx / 288;
            s_w[l][k][col] = wp[((chunk * 8 + l) * 9 + k) * CC + cb * 32 + col];
        }
        __syncthreads();

        // ---- dp4a mainloop: 504 dp4a per ci4-group per thread ----
#pragma unroll
        for (int l = 0; l < 8; ++l) {
#pragma unroll
            for (int kh = 0; kh < 3; ++kh) {
                int xr[9];
#pragma unroll
                for (int i = 0; i < 9; ++i) xr[i] = s_in[l][hh + kh][wbase + i];
#pragma unroll
                for (int kw = 0; kw < 3; ++kw) {
                    const int4* w4 =
                        (const int4*)&s_w[l][kh * 3 + kw][cog * 8];
                    int4 wa = w4[0], wb = w4[1];
                    int wv[8] = {wa.x, wa.y, wa.z, wa.w, wb.x, wb.y, wb.z, wb.w};
#pragma unroll
                    for (int j = 0; j < 8; ++j)
#pragma unroll
                        for (int p = 0; p < 7; ++p)
                            acc[j][p] = __dp4a(xr[kw + p], wv[j], acc[j][p]);
                }
            }
        }
    }

    const int h = h0 + hh;
    if (PHASE == 0) {
        // dequant (/2^11) -> relu -> requant to int8 @ fraclen 5 -> pack.
        // relu(acc/2048)*32 = max(acc,0)/64 ; clip upper 127 (lower inactive).
        const int co4 = (cb * 32 + cog * 8) >> 2;   // first packed group
#pragma unroll
        for (int p = 0; p < 7; ++p) {
            int w = wbase + p;
            int q[8];
#pragma unroll
            for (int j = 0; j < 8; ++j) {
                float y = (float)max(acc[j][p], 0) * (1.0f / 64.0f);
                q[j] = (int)rintf(fminf(y, 127.0f));
            }
            int base = ((n * C4 + co4) * HH_ + h) * WW_ + w;
            g_y1q[base]        = pack4(q[0], q[1], q[2], q[3]);
            g_y1q[base + HW_]  = pack4(q[4], q[5], q[6], q[7]);
        }
    } else {
        // residual in fixed-point scale 2^11 with int32-range clamp, relu.
        // res*2048 == (float)acc exactly; add x*2048, clamp, /2048, relu.
#pragma unroll
        for (int j = 0; j < 8; ++j) {
            int co = cb * 32 + cog * 8 + j;
#pragma unroll
            for (int p = 0; p < 7; ++p) {
                int w  = wbase + p;
                int gi = ((n * CC + co) * HH_ + h) * WW_ + w;
                float s = (float)acc[j][p] + xres[gi] * 2048.0f;
                s = fminf(fmaxf(s, -2147483647.0f), 2147483647.0f);
                out[gi] = fmaxf(s, 0.0f) * (1.0f / 2048.0f);
            }
        }
    }
}

// ---------------- launch ----------------------------------------------------
extern "C" void kernel_launch(void* const* d_in, const int* in_sizes, int n_in,
                              void* d_out, int out_size) {
    const float* x  = (const float*)d_in[0];
    const float* w1 = (const float*)d_in[1];
    const float* w2 = (const float*)d_in[2];
    float* out = (float*)d_out;

    {   // quantize + pack x
        int total = NB * C4 * HW_;
        quant_x_kernel<<<(total + 255) / 256, 256>>>(x);
    }
    {   // pack both weight tensors
        int total = 2 * C4 * 9 * CC;
        pack_w_kernel<<<(total + 255) / 256, 256>>>(w1, w2);
    }
    dim3 grid(HH_ / 8, CC / 32, NB);   // (7, 4, 32)
    conv_kernel<0><<<grid, 256>>>(nullptr, nullptr);
    conv_kernel<1><<<grid, 256>>>(x, out);
}

// round 5
// speedup vs baseline: 1.9604x; 1.9595x over previous
#include <cuda_runtime.h>
#include <cuda_bf16.h>
#include <cstdint>

// Problem dims
#define NB   32
#define CC   128
#define HH_  56
#define WW_  56
#define WP   64          // padded width (w' = spatial w + 1; zeros at 0, 57..63)
#define NCH  4           // ci chunks of 32

// ---------------- scratch (static device globals) ---------------------------
// activation layout: [n][chunk][h][w'][32 ci] bf16, stored as uint32 pairs
__device__ uint32_t g_xb [NB*NCH*HH_*WP*16];
__device__ uint32_t g_y1b[NB*NCH*HH_*WP*16];
__device__ __nv_bfloat16 g_w1b[9*CC*CC];   // [tap][cout][ci]
__device__ __nv_bfloat16 g_w2b[9*CC*CC];

// ---------------- prep: quantize x -> padded bf16 tensor --------------------
// grid (56 h, 4 chunk, 32 n), block 256
__global__ void prep_x(const float* __restrict__ x) {
    __shared__ float s[32][57];
    const int h = blockIdx.x, c4 = blockIdx.y, n = blockIdx.z, t = threadIdx.x;
    for (int idx = t; idx < 32*56; idx += 256) {
        int cc = idx / 56, w = idx % 56;
        float v = x[((n*CC + c4*32 + cc)*HH_ + h)*WW_ + w];
        s[cc][w] = rintf(fminf(fmaxf(v * 32.0f, -128.0f), 127.0f));
    }
    __syncthreads();
    for (int idx = t; idx < WP*16; idx += 256) {
        int wp = idx >> 4, cp = idx & 15;
        uint32_t u = 0;
        if (wp >= 1 && wp <= 56) {
            __nv_bfloat162 p = __floats2bfloat162_rn(s[cp*2][wp-1], s[cp*2+1][wp-1]);
            u = *reinterpret_cast<uint32_t*>(&p);
        }
        g_xb[(((n*NCH + c4)*HH_ + h)*WP + wp)*16 + cp] = u;
    }
}

// ---------------- prep: weights OIHW f32 -> [tap][cout][ci] bf16 ------------
__global__ void prep_w(const float* __restrict__ w1, const float* __restrict__ w2) {
    int idx = blockIdx.x*256 + threadIdx.x;
    const int TOT = 9*CC*64;               // uint32 pairs per tensor
    if (idx >= 2*TOT) return;
    const float* w = (idx < TOT) ? w1 : w2;
    uint32_t*    o = (idx < TOT) ? (uint32_t*)g_w1b : (uint32_t*)g_w2b;
    int e  = (idx < TOT) ? idx : idx - TOT;
    int cp = e & 63, co = (e >> 6) & 127, tp = e >> 13;
    float f0 = w[(co*CC + cp*2    )*9 + tp];
    float f1 = w[(co*CC + cp*2 + 1)*9 + tp];
    __nv_bfloat162 p = __floats2bfloat162_rn(f0, f1);
    o[e] = *reinterpret_cast<uint32_t*>(&p);
}

// ---------------- conv core: mma.sync bf16 ---------------------------------
// block: n (z), cout-group of 32 (y), 8 h-rows (x). 8 warps = 1 h-row each.
// warp tile: M=64 w-pixels x N=32 couts; K = 4 chunks x 9 taps x 32 ci.
static const int IN_ELEMS  = 10*64*40;                 // bf16, 80B padded rows
static const int SMEM_BYTES = (IN_ELEMS + 9*32*40)*2;  // 51200 + 23040 = 74240

template <int PHASE>
__global__ void __launch_bounds__(256, 2)
conv_mma(const float* __restrict__ xres, float* __restrict__ out) {
    extern __shared__ __align__(16) char smem[];
    __nv_bfloat16* in_s = (__nv_bfloat16*)smem;        // [10][64][40]
    __nv_bfloat16* w_s  = in_s + IN_ELEMS;             // [9][32][40]
    const uint32_t*      gin = (PHASE == 0) ? g_xb  : g_y1b;
    const __nv_bfloat16* gw  = (PHASE == 0) ? g_w1b : g_w2b;

    const int n = blockIdx.z, cg = blockIdx.y, h0 = blockIdx.x*8;
    const int t = threadIdx.x, wid = t >> 5, l = t & 31;
    uint32_t in_u = (uint32_t)__cvta_generic_to_shared(in_s);

    float c[4][4][4];
#pragma unroll
    for (int i = 0; i < 4; ++i)
#pragma unroll
        for (int j = 0; j < 4; ++j)
#pragma unroll
            for (int k = 0; k < 4; ++k) c[i][j][k] = 0.0f;

    for (int c4 = 0; c4 < 4; ++c4) {
        __syncthreads();
        // stage input rows h0-1 .. h0+8 (zero pad OOB), 64B/pixel, 80B smem rows
        for (int idx = t; idx < 2560; idx += 256) {
            int r = idx >> 2, u = idx & 3;
            int hi = r >> 6, w = r & 63;
            int hp = h0 + hi - 1;
            uint4 v = make_uint4(0, 0, 0, 0);
            if (hp >= 0 && hp < HH_)
                v = ((const uint4*)(gin + (((n*NCH + c4)*HH_ + hp)*WP + w)*16))[u];
            *(uint4*)((char*)in_s + r*80 + u*16) = v;
        }
        // stage weights: 9 taps x 32 couts x 32 ci
        for (int idx = t; idx < 1152; idx += 256) {
            int r = idx >> 2, u = idx & 3;
            int tap = r >> 5, co = r & 31;
            uint4 v = ((const uint4*)(gw + ((tap*CC + cg*32 + co)*CC + c4*32)))[u];
            *(uint4*)((char*)w_s + r*80 + u*16) = v;
        }
        __syncthreads();

#pragma unroll
        for (int tap = 0; tap < 9; ++tap) {
            const int kh = tap / 3, kw = tap - kh*3;
            // B fragments: lane l -> n = l/4, k = (l%4)*2 (+8 for second reg)
            uint32_t b[4][2][2];
#pragma unroll
            for (int j = 0; j < 4; ++j)
#pragma unroll
                for (int s = 0; s < 2; ++s) {
                    const uint32_t* bp = (const uint32_t*)
                        (w_s + (tap*32 + j*8 + (l >> 2))*40 + s*16 + (l & 3)*2);
                    b[j][s][0] = bp[0];
                    b[j][s][1] = bp[4];
                }
            const int hh = wid + kh;
#pragma unroll
            for (int i = 0; i < 4; ++i) {
                int r  = i*16 + (l & 15);
                int wq = min(max(r + kw - 1, 0), 63);   // clamp only hits invalid outputs
                uint32_t aaddr = in_u + ((hh*64 + wq)*40 + (l >> 4)*8)*2;
#pragma unroll
                for (int s = 0; s < 2; ++s) {
                    uint32_t a0, a1, a2, a3;
                    asm volatile(
                        "ldmatrix.sync.aligned.m8n8.x4.shared.b16 {%0,%1,%2,%3}, [%4];"
                        : "=r"(a0), "=r"(a1), "=r"(a2), "=r"(a3)
                        : "r"(aaddr + s*32));
#pragma unroll
                    for (int j = 0; j < 4; ++j)
                        asm volatile(
                            "mma.sync.aligned.m16n8k16.row.col.f32.bf16.bf16.f32 "
                            "{%0,%1,%2,%3},{%4,%5,%6,%7},{%8,%9},{%0,%1,%2,%3};"
                            : "+f"(c[i][j][0]), "+f"(c[i][j][1]),
                              "+f"(c[i][j][2]), "+f"(c[i][j][3])
                            : "r"(a0), "r"(a1), "r"(a2), "r"(a3),
                              "r"(b[j][s][0]), "r"(b[j][s][1]));
                }
            }
        }
    }

    __syncthreads();
    if (PHASE == 0) {
        // requant: q = rint(min(max(d,0)/64, 127)), store bf16 tensor for conv2
        __nv_bfloat16* y_s = (__nv_bfloat16*)smem;     // [8][64][40]
#pragma unroll
        for (int i = 0; i < 4; ++i)
#pragma unroll
            for (int j = 0; j < 4; ++j) {
                int m1 = i*16 + (l >> 2);
                int ci = j*8 + (l & 3)*2;
                float q0 = rintf(fminf(fmaxf(c[i][j][0], 0.f)*(1.f/64.f), 127.f));
                float q1 = rintf(fminf(fmaxf(c[i][j][1], 0.f)*(1.f/64.f), 127.f));
                float q2 = rintf(fminf(fmaxf(c[i][j][2], 0.f)*(1.f/64.f), 127.f));
                float q3 = rintf(fminf(fmaxf(c[i][j][3], 0.f)*(1.f/64.f), 127.f));
                __nv_bfloat162 pa = __floats2bfloat162_rn(q0, q1);
                __nv_bfloat162 pb = __floats2bfloat162_rn(q2, q3);
                *(uint32_t*)(y_s + (wid*64 + m1    )*40 + ci) = *reinterpret_cast<uint32_t*>(&pa);
                *(uint32_t*)(y_s + (wid*64 + m1 + 8)*40 + ci) = *reinterpret_cast<uint32_t*>(&pb);
            }
        __syncthreads();
        for (int idx = t; idx < 2048; idx += 256) {
            int r = idx >> 2, u = idx & 3;
            int hh = r >> 6, m = r & 63;
            uint4 v = make_uint4(0, 0, 0, 0);
            if (m >= 1 && m <= 56)
                v = *(const uint4*)((char*)y_s + r*80 + u*16);
            ((uint4*)(g_y1b + (((n*NCH + cg)*HH_ + h0 + hh)*WP + m)*16))[u] = v;
        }
    } else {
        // residual add @ scale 2^11, int32-range clamp, relu -> fp32 NCHW
        float* o_s = (float*)smem;                     // [8][64][34]
#pragma unroll
        for (int i = 0; i < 4; ++i)
#pragma unroll
            for (int j = 0; j < 4; ++j) {
                int m1 = i*16 + (l >> 2);
                int co = j*8 + (l & 3)*2;
                *(float2*)(o_s + (wid*64 + m1    )*34 + co) = make_float2(c[i][j][0], c[i][j][1]);
                *(float2*)(o_s + (wid*64 + m1 + 8)*34 + co) = make_float2(c[i][j][2], c[i][j][3]);
            }
        __syncthreads();
        for (int idx = t; idx < 14336; idx += 256) {
            int co  = idx / 448, rem = idx - co*448;
            int hh  = rem / 56,  w   = rem - hh*56;
            float d = o_s[(hh*64 + w + 1)*34 + co];
            int gi  = ((n*CC + cg*32 + co)*HH_ + h0 + hh)*WW_ + w;
            float s = d + xres[gi]*2048.0f;
            s = fminf(fmaxf(s, -2147483647.0f), 2147483647.0f);
            out[gi] = fmaxf(s, 0.0f) * (1.0f/2048.0f);
        }
    }
}

// ---------------- launch -----------------------------------------------------
extern "C" void kernel_launch(void* const* d_in, const int* in_sizes, int n_in,
                              void* d_out, int out_size) {
    const float* x  = (const float*)d_in[0];
    const float* w1 = (const float*)d_in[1];
    const float* w2 = (const float*)d_in[2];
    float* out = (float*)d_out;

    cudaFuncSetAttribute(conv_mma<0>, cudaFuncAttributeMaxDynamicSharedMemorySize, SMEM_BYTES);
    cudaFuncSetAttribute(conv_mma<1>, cudaFuncAttributeMaxDynamicSharedMemorySize, SMEM_BYTES);

    prep_x<<<dim3(56, 4, 32), 256>>>(x);
    prep_w<<<(2*9*CC*64 + 255)/256, 256>>>(w1, w2);

    dim3 grid(7, 4, 32);
    conv_mma<0><<<grid, 256, SMEM_BYTES>>>(nullptr, nullptr);
    conv_mma<1><<<grid, 256, SMEM_BYTES>>>(x, out);
}

// round 7
// speedup vs baseline: 3.3860x; 1.7272x over previous
#include <cuda_runtime.h>
#include <cuda_bf16.h>
#include <cstdint>

#define NB   32
#define CC   128
#define HH_  56
#define WW_  56

// activations int8, packed: [n][chunk 4][h 56][w' 64][ci 32] (w'=w+1, zero cols 0,57-63)
__device__ uint32_t g_xq [NB*4*HH_*64*8];
__device__ uint32_t g_y1q[NB*4*HH_*64*8];
// weights int8: [T 2][chunk 4][tap 9][cout 128][ci 32]
__device__ uint32_t g_wq [2*4*9*CC*8];

// ---------------- prep: quantize x -> packed int8 ---------------------------
// grid (56 h, 32 n), block 256
__global__ void prep_x(const float* __restrict__ x) {
    __shared__ char s[CC][WW_];
    const int h = blockIdx.x, n = blockIdx.y, t = threadIdx.x;
    for (int i = t; i < CC*WW_; i += 256) {
        int c = i / WW_, w = i % WW_;
        float v = x[((n*CC + c)*HH_ + h)*WW_ + w];
        s[c][w] = (char)(int)rintf(fminf(fmaxf(v * 32.0f, -128.0f), 127.0f));
    }
    __syncthreads();
    for (int i = t; i < 4*64*8; i += 256) {
        int u = i & 7, wp = (i >> 3) & 63, ch = i >> 9;
        uint32_t word = 0;
        if (wp >= 1 && wp <= 56) {
            int ci = ch*32 + u*4, w = wp - 1;
            word = ((uint32_t)(uint8_t)s[ci][w])
                 | ((uint32_t)(uint8_t)s[ci+1][w] << 8)
                 | ((uint32_t)(uint8_t)s[ci+2][w] << 16)
                 | ((uint32_t)(uint8_t)s[ci+3][w] << 24);
        }
        g_xq[(((n*4 + ch)*HH_ + h)*64 + wp)*8 + u] = word;
    }
}

// ---------------- prep: weights OIHW f32 -> packed int8 ---------------------
__global__ void prep_w(const float* __restrict__ w1, const float* __restrict__ w2) {
    int idx = blockIdx.x*256 + threadIdx.x;
    const int PER = 4*9*CC*8;                 // 36864 words per tensor
    if (idx >= 2*PER) return;
    const float* w = (idx < PER) ? w1 : w2;
    int e = (idx < PER) ? idx : idx - PER;
    int u = e & 7, co = (e >> 3) & 127, g = e >> 10;
    int tap = g % 9, ch = g / 9;
    uint32_t word = 0;
#pragma unroll
    for (int b = 0; b < 4; ++b) {
        int ci = ch*32 + u*4 + b;
        int q = (int)rintf(w[(co*CC + ci)*9 + tap]);
        word |= (uint32_t)(q & 255) << (8*b);
    }
    g_wq[idx] = word;
}

// ---------------- conv core: mma.sync int8 m16n8k32 -------------------------
// block: n (z), cout-group of 32 (y), 8 h-rows (x). 8 warps = 1 h-row each.
// warp tile: M=64 w-pixels x N=32 couts; K = 4 chunks x 9 taps x 32 ci.
// smem rows padded to 48B (12-word stride: conflict-free ldmatrix + LDS).
static const int XS_BYTES = 10*64*48;         // 30720
static const int WS_BYTES = 9*32*48;          // 13824
static const int SM_BYTES = XS_BYTES + WS_BYTES;   // 44544 (< 48K static)

template <int PHASE>
__global__ void __launch_bounds__(256, 2)
conv_imma(const float* __restrict__ xres, float* __restrict__ out) {
    __shared__ __align__(16) char smem[SM_BYTES];
    char* Xs = smem;
    char* Ws = smem + XS_BYTES;
    const uint4* gin4 = (const uint4*)(PHASE == 0 ? g_xq : g_y1q);
    const uint4* gw4  = (const uint4*)g_wq + (size_t)PHASE*4*9*CC*2;

    const int n = blockIdx.z, cg = blockIdx.y, h0 = blockIdx.x*8;
    const int t = threadIdx.x, wid = t >> 5, l = t & 31;
    const uint32_t Xu = (uint32_t)__cvta_generic_to_shared(Xs);

    int c[4][4][4];
#pragma unroll
    for (int i = 0; i < 4; ++i)
#pragma unroll
        for (int j = 0; j < 4; ++j)
#pragma unroll
            for (int k = 0; k < 4; ++k) c[i][j][k] = 0;

    for (int ch = 0; ch < 4; ++ch) {
        __syncthreads();
        // stage X: 10 rows (h0-1..h0+8) x 64 w', 32B/pixel -> 48B smem rows
        for (int i = t; i < 640; i += 256) {
            int hr = i >> 6, w = i & 63;
            int h = h0 + hr - 1;
            uint4 v0 = make_uint4(0,0,0,0), v1 = v0;
            if (h >= 0 && h < HH_) {
                const uint4* p = gin4 + ((((n*4 + ch)*HH_ + h)*64 + w) << 1);
                v0 = p[0]; v1 = p[1];
            }
            char* d = Xs + (hr*64 + w)*48;
            *(uint4*)d        = v0;
            *(uint4*)(d + 16) = v1;
        }
        // stage W: 9 taps x 32 couts, 32B each -> 48B rows
        for (int i = t; i < 288; i += 256) {
            int tap = i / 32, co = i & 31;
            const uint4* p = gw4 + (((ch*9 + tap)*CC + cg*32 + co) << 1);
            char* d = Ws + (tap*32 + co)*48;
            uint4 v0 = p[0], v1 = p[1];
            *(uint4*)d        = v0;
            *(uint4*)(d + 16) = v1;
        }
        __syncthreads();

#pragma unroll
        for (int tap = 0; tap < 9; ++tap) {
            const int kh = tap/3, kw = tap - kh*3;
            // B fragments: n = j*8 + l/4, k-bytes (l%4)*4 (+16)
            uint32_t b[4][2];
#pragma unroll
            for (int j = 0; j < 4; ++j) {
                const char* bp = Ws + (tap*32 + j*8 + (l >> 2))*48 + (l & 3)*4;
                b[j][0] = *(const uint32_t*)bp;
                b[j][1] = *(const uint32_t*)(bp + 16);
            }
            const int hh = wid + kh;
#pragma unroll
            for (int i = 0; i < 4; ++i) {
                int p = min(max(i*16 + (l & 15) + kw - 1, 0), 63);
                uint32_t aaddr = Xu + (hh*64 + p)*48 + (l >> 4)*16;
                uint32_t a0, a1, a2, a3;
                asm volatile(
                    "ldmatrix.sync.aligned.m8n8.x4.shared.b16 {%0,%1,%2,%3}, [%4];"
                    : "=r"(a0), "=r"(a1), "=r"(a2), "=r"(a3) : "r"(aaddr));
#pragma unroll
                for (int j = 0; j < 4; ++j)
                    asm volatile(
                        "mma.sync.aligned.m16n8k32.row.col.s32.s8.s8.s32 "
                        "{%0,%1,%2,%3},{%4,%5,%6,%7},{%8,%9},{%0,%1,%2,%3};"
                        : "+r"(c[i][j][0]), "+r"(c[i][j][1]),
                          "+r"(c[i][j][2]), "+r"(c[i][j][3])
                        : "r"(a0), "r"(a1), "r"(a2), "r"(a3),
                          "r"(b[j][0]), "r"(b[j][1]));
            }
        }
    }
    __syncthreads();

    if (PHASE == 0) {
        // requant int8 and stage [h 8][w' 64][ci 32] for coalesced store
        uint16_t* Yb = (uint16_t*)smem;
#pragma unroll
        for (int i = 0; i < 4; ++i)
#pragma unroll
            for (int j = 0; j < 4; ++j) {
                int m0 = i*16 + (l >> 2);
                int nn = j*8 + (l & 3)*2;
#pragma unroll
                for (int hseg = 0; hseg < 2; ++hseg) {
                    int m = m0 + hseg*8;
                    int q0 = (int)rintf(fminf((float)max(c[i][j][hseg*2  ], 0)*(1.f/64.f), 127.f));
                    int q1 = (int)rintf(fminf((float)max(c[i][j][hseg*2+1], 0)*(1.f/64.f), 127.f));
                    Yb[((wid*64 + m)*32 + nn) >> 1] =
                        (uint16_t)((q0 & 255) | ((q1 & 255) << 8));
                }
            }
        __syncthreads();
        uint4* gy = (uint4*)g_y1q;
        for (int i = t; i < 512; i += 256) {
            int hr = i >> 6, w = i & 63;
            uint4 v0 = make_uint4(0,0,0,0), v1 = v0;
            if (w >= 1 && w <= 56) {
                const uint4* p = (const uint4*)(smem + (hr*64 + w)*32);
                v0 = p[0]; v1 = p[1];
            }
            uint4* d = gy + ((((n*4 + cg)*HH_ + h0 + hr)*64 + w) << 1);
            d[0] = v0; d[1] = v1;
        }
    } else {
        // residual add @ scale 2^11, clamp, relu -> fp32 NCHW; 2 passes of 16 couts
        float* Fst = (float*)smem;             // [co 16] stride 532, [h 8] stride 66
        for (int pass = 0; pass < 2; ++pass) {
#pragma unroll
            for (int j2 = 0; j2 < 2; ++j2) {
                int j = pass*2 + j2;
#pragma unroll
                for (int i = 0; i < 4; ++i) {
                    int nloc = j2*8 + (l & 3)*2;
                    int m0 = i*16 + (l >> 2);
                    Fst[ nloc   *532 + wid*66 + m0    ] = (float)c[i][j][0];
                    Fst[(nloc+1)*532 + wid*66 + m0    ] = (float)c[i][j][1];
                    Fst[ nloc   *532 + wid*66 + m0 + 8] = (float)c[i][j][2];
                    Fst[(nloc+1)*532 + wid*66 + m0 + 8] = (float)c[i][j][3];
                }
            }
            __syncthreads();
            for (int i = t; i < 16*8*56; i += 256) {
                int co = i / 448, rem = i - co*448;
                int hr = rem / 56, w = rem - hr*56;
                float d = Fst[co*532 + hr*66 + w + 1];
                int gi = ((n*CC + cg*32 + pass*16 + co)*HH_ + h0 + hr)*WW_ + w;
                float s = d + xres[gi]*2048.0f;
                s = fminf(fmaxf(s, -2147483647.0f), 2147483647.0f);
                out[gi] = fmaxf(s, 0.0f) * (1.0f/2048.0f);
            }
            __syncthreads();
        }
    }
}

// ---------------- launch -----------------------------------------------------
extern "C" void kernel_launch(void* const* d_in, const int* in_sizes, int n_in,
                              void* d_out, int out_size) {
    const float* x  = (const float*)d_in[0];
    const float* w1 = (const float*)d_in[1];
    const float* w2 = (const float*)d_in[2];
    float* out = (float*)d_out;

    prep_x<<<dim3(HH_, NB), 256>>>(x);
    prep_w<<<(2*4*9*CC*8 + 255)/256, 256>>>(w1, w2);

    dim3 grid(7, 4, 32);
    conv_imma<0><<<grid, 256>>>(nullptr, nullptr);
    conv_imma<1><<<grid, 256>>>(x, out);
}